// round 1
// baseline (speedup 1.0000x reference)
#include <cuda_runtime.h>
#include <cuda_bf16.h>
#include <math.h>

#define NN 1024
#define FEAT 2048
#define H 256

// ---------------- scratch (device globals; no allocation allowed) ----------
__device__ float g_X1[NN * H];
__device__ float g_h[NN * H];
__device__ float g_X2[NN * H];
__device__ float g_di[NN * H];
__device__ float g_hi[NN * H];
__device__ float g_hjb[NN * H];
__device__ float g_E[NN * NN];
__device__ float g_scale1[H], g_shift1[H];
__device__ float g_scale2[H], g_shift2[H];
__device__ float g_wsum[NN];

// ---------------- generic tiled SGEMM: C[M,N] = A[M,K] @ B[K,N] -------------
// BM=32, BN=64, BK=16, thread tile 2x4, 256 threads.
// EPI==0: C = AB + bias (bias may be null)
// EPI==1: C = addend + AB * (wsum[row]>0 ? 1/wsum[row] : 0)
template <int EPI>
__global__ void sgemm32x64(const float* __restrict__ A, const float* __restrict__ B,
                           float* __restrict__ C, int M, int N, int K,
                           const float* __restrict__ bias,
                           const float* __restrict__ addend,
                           const float* __restrict__ wsum) {
    constexpr int BM = 32, BN = 64, BK = 16;
    __shared__ float As[BK][BM + 1];
    __shared__ __align__(16) float Bs[BK][BN];

    const int t = threadIdx.x;          // 0..255
    const int tx = t & 15;              // N dir (x4)
    const int ty = t >> 4;              // M dir (x2)
    const int I = blockIdx.y * BM;
    const int J = blockIdx.x * BN;

    float4 acc0 = make_float4(0.f, 0.f, 0.f, 0.f);
    float4 acc1 = make_float4(0.f, 0.f, 0.f, 0.f);

    for (int k0 = 0; k0 < K; k0 += BK) {
        // load A tile (32x16 = 512 elems, 2 per thread), stored transposed
#pragma unroll
        for (int e = 0; e < 2; e++) {
            int idx = t + e * 256;
            int r = idx >> 4, c = idx & 15;
            As[c][r] = A[(size_t)(I + r) * K + k0 + c];
        }
        // load B tile (16x64 = 1024 elems, float4 per thread)
        {
            int r = t >> 4, c4 = t & 15;
            *(float4*)&Bs[r][c4 * 4] =
                *(const float4*)&B[(size_t)(k0 + r) * N + J + c4 * 4];
        }
        __syncthreads();
#pragma unroll
        for (int k = 0; k < BK; k++) {
            float a0 = As[k][ty * 2];
            float a1 = As[k][ty * 2 + 1];
            float4 b = *(float4*)&Bs[k][tx * 4];
            acc0.x = fmaf(a0, b.x, acc0.x);
            acc0.y = fmaf(a0, b.y, acc0.y);
            acc0.z = fmaf(a0, b.z, acc0.z);
            acc0.w = fmaf(a0, b.w, acc0.w);
            acc1.x = fmaf(a1, b.x, acc1.x);
            acc1.y = fmaf(a1, b.y, acc1.y);
            acc1.z = fmaf(a1, b.z, acc1.z);
            acc1.w = fmaf(a1, b.w, acc1.w);
        }
        __syncthreads();
    }

    const int col = J + tx * 4;
#pragma unroll
    for (int ii = 0; ii < 2; ii++) {
        int row = I + ty * 2 + ii;
        float4 a = ii ? acc1 : acc0;
        if (EPI == 0) {
            if (bias) {
                float4 bb = *(const float4*)&bias[col];
                a.x += bb.x; a.y += bb.y; a.z += bb.z; a.w += bb.w;
            }
        } else {
            float ws = wsum[row];
            float inv = ws > 0.f ? 1.f / ws : 0.f;
            float4 d = *(const float4*)&addend[(size_t)row * N + col];
            a.x = fmaf(a.x, inv, d.x);
            a.y = fmaf(a.y, inv, d.y);
            a.z = fmaf(a.z, inv, d.z);
            a.w = fmaf(a.w, inv, d.w);
        }
        *(float4*)&C[(size_t)row * N + col] = a;
    }
}

// ---------------- BatchNorm stats: per-column mean/var -> scale/shift -------
__global__ void bn_stats(const float* __restrict__ X, const float* __restrict__ g,
                         const float* __restrict__ bt, float* __restrict__ scale,
                         float* __restrict__ shift) {
    const int c = blockIdx.x;  // column 0..255
    const int t = threadIdx.x; // 256 threads
    float s = 0.f, sq = 0.f;
#pragma unroll
    for (int r = t; r < NN; r += 256) {
        float v = X[(size_t)r * H + c];
        s += v;
        sq += v * v;
    }
    __shared__ float ss[256], sqq[256];
    ss[t] = s; sqq[t] = sq;
    __syncthreads();
    for (int o = 128; o > 0; o >>= 1) {
        if (t < o) { ss[t] += ss[t + o]; sqq[t] += sqq[t + o]; }
        __syncthreads();
    }
    if (t == 0) {
        float m = ss[0] * (1.f / NN);
        float var = sqq[0] * (1.f / NN) - m * m;
        float rstd = rsqrtf(var + 1e-5f);
        float sc = g[c] * rstd;
        scale[c] = sc;
        shift[c] = bt[c] - m * sc;
    }
}

// ---------------- BN apply + ReLU (elementwise, float4) ---------------------
__global__ void bn_apply_relu(const float* __restrict__ X,
                              const float* __restrict__ scale,
                              const float* __restrict__ shift,
                              float* __restrict__ Y) {
    int idx = blockIdx.x * blockDim.x + threadIdx.x;  // float4 index, 65536 total
    float4 x = ((const float4*)X)[idx];
    int c4 = idx & 63;  // (idx*4) % 256 / 4
    float4 sc = ((const float4*)scale)[c4];
    float4 sh = ((const float4*)shift)[c4];
    float4 y;
    y.x = fmaxf(fmaf(x.x, sc.x, sh.x), 0.f);
    y.y = fmaxf(fmaf(x.y, sc.y, sh.y), 0.f);
    y.z = fmaxf(fmaf(x.z, sc.z, sh.z), 0.f);
    y.w = fmaxf(fmaf(x.w, sc.w, sh.w), 0.f);
    ((float4*)Y)[idx] = y;
}

// ---------------- Edge network all-pairs kernel ------------------------------
// logits[i,j] = sum_h relu(hi[i,h] + hjb[j,h]) * We2[h] + bwe2
// E[i,j] = (labels[i]==labels[j] && i!=j) ? sigmoid(logits) : 0
// Block computes 32x32 (i,j) tile; 256 threads, each 2x2 pairs.
__global__ void edge_kernel(const float* __restrict__ hi, const float* __restrict__ hjb,
                            const float* __restrict__ We2, const float* __restrict__ bwe2,
                            const int* __restrict__ labels, float* __restrict__ E) {
    __shared__ float shi[64][33];
    __shared__ float shj[64][33];
    __shared__ float wsh[H];
    __shared__ int li[32], lj[32];

    const int I = blockIdx.y * 32;
    const int J = blockIdx.x * 32;
    const int t = threadIdx.x;  // 0..255
    const int tx = t & 15;
    const int ty = t >> 4;

    if (t < H) wsh[t] = We2[t];
    if (t < 32) li[t] = labels[I + t];
    else if (t < 64) lj[t - 32] = labels[J + t - 32];

    float acc00 = 0.f, acc01 = 0.f, acc10 = 0.f, acc11 = 0.f;

    for (int hc = 0; hc < H; hc += 64) {
        __syncthreads();
#pragma unroll
        for (int e = 0; e < 8; e++) {
            int idx = t + e * 256;     // 0..2047
            int r = idx >> 6;          // node 0..31
            int c = idx & 63;          // h within chunk
            shi[c][r] = hi[(size_t)(I + r) * H + hc + c];
            shj[c][r] = hjb[(size_t)(J + r) * H + hc + c];
        }
        __syncthreads();
#pragma unroll
        for (int h = 0; h < 64; h++) {
            float w = wsh[hc + h];
            float a0 = shi[h][ty * 2];
            float a1 = shi[h][ty * 2 + 1];
            float b0 = shj[h][tx * 2];
            float b1 = shj[h][tx * 2 + 1];
            acc00 = fmaf(fmaxf(a0 + b0, 0.f), w, acc00);
            acc01 = fmaf(fmaxf(a0 + b1, 0.f), w, acc01);
            acc10 = fmaf(fmaxf(a1 + b0, 0.f), w, acc10);
            acc11 = fmaf(fmaxf(a1 + b1, 0.f), w, acc11);
        }
    }

    const float bw = bwe2[0];
    const int i0 = I + 2 * ty, i1 = i0 + 1;
    const int j0 = J + 2 * tx, j1 = j0 + 1;
    const int la0 = li[2 * ty], la1 = li[2 * ty + 1];
    const int lb0 = lj[2 * tx], lb1 = lj[2 * tx + 1];

    float e00 = (la0 == lb0 && i0 != j0) ? 1.f / (1.f + expf(-(acc00 + bw))) : 0.f;
    float e01 = (la0 == lb1 && i0 != j1) ? 1.f / (1.f + expf(-(acc01 + bw))) : 0.f;
    float e10 = (la1 == lb0 && i1 != j0) ? 1.f / (1.f + expf(-(acc10 + bw))) : 0.f;
    float e11 = (la1 == lb1 && i1 != j1) ? 1.f / (1.f + expf(-(acc11 + bw))) : 0.f;

    *(float2*)&E[(size_t)i0 * NN + j0] = make_float2(e00, e01);
    *(float2*)&E[(size_t)i1 * NN + j0] = make_float2(e10, e11);
}

// ---------------- deterministic row sum of E --------------------------------
__global__ void row_sum(const float* __restrict__ E, float* __restrict__ wsum) {
    const int i = blockIdx.x;
    const int t = threadIdx.x;  // 256
    float s = 0.f;
#pragma unroll
    for (int j = t; j < NN; j += 256) s += E[(size_t)i * NN + j];
    __shared__ float ss[256];
    ss[t] = s;
    __syncthreads();
    for (int o = 128; o > 0; o >>= 1) {
        if (t < o) ss[t] += ss[t + o];
        __syncthreads();
    }
    if (t == 0) wsum[i] = ss[0];
}

// ---------------- launch -----------------------------------------------------
extern "C" void kernel_launch(void* const* d_in, const int* in_sizes, int n_in,
                              void* d_out, int out_size) {
    const float* features = (const float*)d_in[0];
    const int* labels = (const int*)d_in[1];
    const float* W1 = (const float*)d_in[2];
    const float* b1 = (const float*)d_in[3];
    const float* g1 = (const float*)d_in[4];
    const float* bt1 = (const float*)d_in[5];
    const float* W2 = (const float*)d_in[6];
    const float* b2 = (const float*)d_in[7];
    const float* g2 = (const float*)d_in[8];
    const float* bt2 = (const float*)d_in[9];
    const float* We1 = (const float*)d_in[10];
    const float* bwe1 = (const float*)d_in[11];
    const float* We2 = (const float*)d_in[12];
    const float* bwe2 = (const float*)d_in[13];
    float* out = (float*)d_out;

    void *pX1, *ph, *pX2, *pdi, *phi, *phjb, *pE;
    void *psc1, *psh1, *psc2, *psh2, *pws;
    cudaGetSymbolAddress(&pX1, g_X1);
    cudaGetSymbolAddress(&ph, g_h);
    cudaGetSymbolAddress(&pX2, g_X2);
    cudaGetSymbolAddress(&pdi, g_di);
    cudaGetSymbolAddress(&phi, g_hi);
    cudaGetSymbolAddress(&phjb, g_hjb);
    cudaGetSymbolAddress(&pE, g_E);
    cudaGetSymbolAddress(&psc1, g_scale1);
    cudaGetSymbolAddress(&psh1, g_shift1);
    cudaGetSymbolAddress(&psc2, g_scale2);
    cudaGetSymbolAddress(&psh2, g_shift2);
    cudaGetSymbolAddress(&pws, g_wsum);

    float* X1 = (float*)pX1;
    float* h = (float*)ph;
    float* X2 = (float*)pX2;
    float* di = (float*)pdi;
    float* hi = (float*)phi;
    float* hjb = (float*)phjb;
    float* E = (float*)pE;
    float* sc1 = (float*)psc1;
    float* sh1 = (float*)psh1;
    float* sc2 = (float*)psc2;
    float* sh2 = (float*)psh2;
    float* ws = (float*)pws;

    dim3 gemmGridH(H / 64, NN / 32);  // (4, 32)

    // 1) X1 = features @ W1 + b1   [1024x2048 @ 2048x256]
    sgemm32x64<0><<<gemmGridH, 256>>>(features, W1, X1, NN, H, FEAT, b1, nullptr, nullptr);
    // 2) BN1 stats -> scale/shift
    bn_stats<<<H, 256>>>(X1, g1, bt1, sc1, sh1);
    // 3) h = relu(BN1(X1))
    bn_apply_relu<<<(NN * H / 4) / 256, 256>>>(X1, sc1, sh1, h);
    // 4) X2 = h @ W2 + b2
    sgemm32x64<0><<<gemmGridH, 256>>>(h, W2, X2, NN, H, H, b2, nullptr, nullptr);
    // 5) BN2 stats
    bn_stats<<<H, 256>>>(X2, g2, bt2, sc2, sh2);
    // 6) di = relu(BN2(X2))
    bn_apply_relu<<<(NN * H / 4) / 256, 256>>>(X2, sc2, sh2, di);
    // 7) hi = di @ We1[:H]
    sgemm32x64<0><<<gemmGridH, 256>>>(di, We1, hi, NN, H, H, nullptr, nullptr, nullptr);
    // 8) hjb = di @ We1[H:] + bwe1
    sgemm32x64<0><<<gemmGridH, 256>>>(di, We1 + H * H, hjb, NN, H, H, bwe1, nullptr, nullptr);
    // 9) edge weights E [1024x1024]
    edge_kernel<<<dim3(NN / 32, NN / 32), 256>>>(hi, hjb, We2, bwe2, labels, E);
    // 10) wsum[i] = sum_j E[i,j] (deterministic)
    row_sum<<<NN, 256>>>(E, ws);
    // 11) out = di + (E @ di) / wsum  (where wsum > 0)
    sgemm32x64<1><<<gemmGridH, 256>>>(E, di, out, NN, H, NN, nullptr, di, ws);
}

// round 2
// speedup vs baseline: 1.4324x; 1.4324x over previous
#include <cuda_runtime.h>
#include <cuda_bf16.h>
#include <math.h>

#define NN 1024
#define H 256

typedef unsigned long long u64;

// ---------------- f32x2 packed helpers (sm_103a) ----------------------------
__device__ __forceinline__ u64 add2(u64 a, u64 b) {
    u64 r; asm("add.rn.f32x2 %0,%1,%2;" : "=l"(r) : "l"(a), "l"(b)); return r;
}
__device__ __forceinline__ void fma2(u64& d, u64 a, u64 b) {
    asm("fma.rn.f32x2 %0,%1,%2,%0;" : "+l"(d) : "l"(a), "l"(b));
}
__device__ __forceinline__ float2 unpack2(u64 v) {
    float2 r; asm("mov.b64 {%0,%1},%2;" : "=f"(r.x), "=f"(r.y) : "l"(v)); return r;
}

// ---------------- scratch ----------------------------------------------------
__device__ float g_P[4 * NN * H];   // split-K partials (reused)
__device__ float g_h[NN * H];
__device__ float g_di[NN * H];
__device__ float g_hi[NN * H];
__device__ float g_hjb[NN * H];
__device__ float g_E[NN * NN];
__device__ float g_sc[H], g_sh[H];
__device__ float g_ci[NN], g_dj[NN];
__device__ float g_wsum[NN];

// ---------------- GEMM: C[1024, 256] = A[1024, K] @ B[K, 256] ---------------
// BN=64, BK=16, thread tile 4x4, K-packed f32x2 accumulation.
// MODE 0: C0 = AB (+bias0)
// MODE 1: split-K partial: z-th chunk of K (length KS) -> C0 + z*1024*256
// MODE 2: dual: z=0 -> C0 = A@B[:256] ; z=1 -> C1 = A@B[256:] + bias1
template <int BM, int MODE>
__global__ void gemm_v2(const float* __restrict__ A, const float* __restrict__ B,
                        float* __restrict__ C0, float* __restrict__ C1,
                        int K, int KS,
                        const float* __restrict__ bias0, const float* __restrict__ bias1) {
    constexpr int T = BM * 4;  // threads (256 or 128)
    __shared__ float As[BM][18];
    __shared__ float Bs[64][18];

    const int t = threadIdx.x;
    const int tx = t & 15;       // 16 cols groups
    const int ty = t >> 4;       // BM/4 row groups
    const int I = blockIdx.y * BM;
    const int J = blockIdx.x * 64;
    const int z = blockIdx.z;

    const float* Bp = B;
    float* Cp = C0;
    const float* bp = (MODE == 0) ? bias0 : nullptr;
    int kbase = 0;
    if (MODE == 1) { kbase = z * KS; Cp = C0 + (size_t)z * NN * H; }
    if (MODE == 2) {
        if (z) { Bp = B + 256 * 256; Cp = C1; bp = bias1; }
        else   { bp = nullptr; }
    }

    u64 acc[4][4];
#pragma unroll
    for (int m = 0; m < 4; m++)
#pragma unroll
        for (int n = 0; n < 4; n++) acc[m][n] = 0ull;

    const int kiters = ((MODE == 1) ? KS : K) >> 4;
    for (int kt = 0; kt < kiters; kt++) {
        const int k0 = kbase + kt * 16;
        // load A tile BMx16, store transposed As[m][k]
        {
            const int c = t & 15;
            const int r0 = t >> 4;          // 0..T/16-1
            constexpr int RS = T / 16;
#pragma unroll
            for (int e = 0; e < BM / RS; e++) {
                int r = r0 + e * RS;
                As[r][c] = A[(size_t)(I + r) * K + k0 + c];
            }
        }
        // load B tile 16x64, store transposed Bs[n][k]
        {
            const int c = t & 63;
            const int r0 = t >> 6;          // 0..T/64-1
            constexpr int RS2 = T / 64;
#pragma unroll
            for (int e = 0; e < 16 / RS2; e++) {
                int r = r0 + e * RS2;
                Bs[c][r] = Bp[(size_t)(k0 + r) * H + J + c];
            }
        }
        __syncthreads();
#pragma unroll
        for (int kp = 0; kp < 8; kp++) {
            u64 aP[4], bP[4];
#pragma unroll
            for (int m = 0; m < 4; m++)
                aP[m] = *(const u64*)&As[ty * 4 + m][kp * 2];
#pragma unroll
            for (int n = 0; n < 4; n++)
                bP[n] = *(const u64*)&Bs[tx + n * 16][kp * 2];
#pragma unroll
            for (int m = 0; m < 4; m++)
#pragma unroll
                for (int n = 0; n < 4; n++) fma2(acc[m][n], aP[m], bP[n]);
        }
        __syncthreads();
    }

#pragma unroll
    for (int m = 0; m < 4; m++) {
        const int row = I + ty * 4 + m;
#pragma unroll
        for (int n = 0; n < 4; n++) {
            const int col = J + tx + n * 16;
            float2 p = unpack2(acc[m][n]);
            float v = p.x + p.y;
            if (bp) v += bp[col];
            Cp[(size_t)row * H + col] = v;
        }
    }
}

// ---------------- BN stats over 4 split-K partials (+bias) ------------------
// grid 8 blocks x 512 threads; block handles 32 columns.
__global__ void bn_stats_part(const float* __restrict__ P, const float* __restrict__ bias,
                              const float* __restrict__ g, const float* __restrict__ bt,
                              float* __restrict__ scale, float* __restrict__ shift) {
    const int t = threadIdx.x;
    const int col = blockIdx.x * 32 + (t & 31);
    const int rg = t >> 5;  // 0..15
    const float bv = bias[col];
    float s = 0.f, sq = 0.f;
    for (int r = rg; r < NN; r += 16) {
        size_t off = (size_t)r * H + col;
        float v = bv + P[off] + P[NN * H + off] + P[2 * NN * H + off] + P[3 * NN * H + off];
        s += v; sq += v * v;
    }
    __shared__ float sm[16][32], sm2[16][32];
    sm[rg][t & 31] = s;
    sm2[rg][t & 31] = sq;
    __syncthreads();
    if (t < 32) {
        float S = 0.f, Q = 0.f;
#pragma unroll
        for (int i = 0; i < 16; i++) { S += sm[i][t]; Q += sm2[i][t]; }
        const int c = blockIdx.x * 32 + t;
        float m = S * (1.f / NN);
        float var = Q * (1.f / NN) - m * m;
        float sc = g[c] * rsqrtf(var + 1e-5f);
        scale[c] = sc;
        shift[c] = bt[c] - m * sc;
    }
}

// ---------------- BN apply + ReLU from 4 partials ---------------------------
__global__ void bn_apply_part(const float* __restrict__ P, const float* __restrict__ bias,
                              const float* __restrict__ scale, const float* __restrict__ shift,
                              float* __restrict__ Y) {
    const int idx = blockIdx.x * 256 + threadIdx.x;  // float4 index, 65536 total
    const int c4 = idx & 63;
    const float4* P4 = (const float4*)P;
    float4 v = ((const float4*)bias)[c4];
    constexpr int Q = NN * H / 4;
    float4 a = P4[idx], b = P4[Q + idx], c = P4[2 * Q + idx], d = P4[3 * Q + idx];
    v.x += a.x + b.x + c.x + d.x;
    v.y += a.y + b.y + c.y + d.y;
    v.z += a.z + b.z + c.z + d.z;
    v.w += a.w + b.w + c.w + d.w;
    float4 sc = ((const float4*)scale)[c4];
    float4 sh = ((const float4*)shift)[c4];
    float4 y;
    y.x = fmaxf(fmaf(v.x, sc.x, sh.x), 0.f);
    y.y = fmaxf(fmaf(v.y, sc.y, sh.y), 0.f);
    y.z = fmaxf(fmaf(v.z, sc.z, sh.z), 0.f);
    y.w = fmaxf(fmaf(v.w, sc.w, sh.w), 0.f);
    ((float4*)Y)[idx] = y;
}

// ---------------- ci / dj GEMVs: 0.5 * (rows @ We2) --------------------------
__global__ void cidj_kernel(const float* __restrict__ hi, const float* __restrict__ hjb,
                            const float* __restrict__ We2,
                            float* __restrict__ ci, float* __restrict__ dj) {
    const int gt = blockIdx.x * 256 + threadIdx.x;
    const int w = gt >> 5;          // global warp = row id (0..2047)
    const int lane = gt & 31;
    const float* src = (w < NN) ? hi : hjb;
    const int row = (w < NN) ? w : w - NN;
    float s = 0.f;
#pragma unroll
    for (int e = 0; e < 8; e++) {
        int c = lane + e * 32;
        s = fmaf(src[(size_t)row * H + c], We2[c], s);
    }
#pragma unroll
    for (int o = 16; o > 0; o >>= 1) s += __shfl_xor_sync(~0u, s, o);
    if (lane == 0) ((w < NN) ? ci : dj)[row] = 0.5f * s;
}

// ---------------- Edge kernel: 64x64 tile, f32x2 h-packed -------------------
// logit = 0.5*sum_h w|a+b| + ci[i] + dj[j] + bwe2 ; E = mask ? sigmoid : 0
__global__ void edge_kernel(const float* __restrict__ hi, const float* __restrict__ hjb,
                            const float* __restrict__ We2, const float* __restrict__ bwe2,
                            const int* __restrict__ labels,
                            const float* __restrict__ ci, const float* __restrict__ dj,
                            float* __restrict__ E) {
    __shared__ float sa[64][66];
    __shared__ float sb[64][66];
    __shared__ float sw[64];
    __shared__ int li[64], lj[64];
    __shared__ float sci[64], sdj[64];

    const int t = threadIdx.x;
    const int tx = t & 15;
    const int ty = t >> 4;
    const int I = blockIdx.y * 64;
    const int J = blockIdx.x * 64;

    if (t < 64) {
        li[t] = labels[I + t];
        lj[t] = labels[J + t];
        sci[t] = ci[I + t];
        sdj[t] = dj[J + t];
    }

    u64 acc[4][4];
#pragma unroll
    for (int m = 0; m < 4; m++)
#pragma unroll
        for (int n = 0; n < 4; n++) acc[m][n] = 0ull;

    for (int hc = 0; hc < H; hc += 64) {
        __syncthreads();
        {
            const int r = t >> 2;
            const int c0 = (t & 3) * 16;
            const float* pa = &hi[(size_t)(I + r) * H + hc + c0];
            const float* pb = &hjb[(size_t)(J + r) * H + hc + c0];
#pragma unroll
            for (int e = 0; e < 4; e++) {
                float4 va = *(const float4*)(pa + e * 4);
                float4 vb = *(const float4*)(pb + e * 4);
                *(float2*)&sa[r][c0 + e * 4]     = make_float2(va.x, va.y);
                *(float2*)&sa[r][c0 + e * 4 + 2] = make_float2(va.z, va.w);
                *(float2*)&sb[r][c0 + e * 4]     = make_float2(vb.x, vb.y);
                *(float2*)&sb[r][c0 + e * 4 + 2] = make_float2(vb.z, vb.w);
            }
            if (t < 64) sw[t] = 0.5f * We2[hc + t];
        }
        __syncthreads();
#pragma unroll 8
        for (int hp = 0; hp < 32; hp++) {
            u64 wP = *(const u64*)&sw[hp * 2];
            u64 aP[4], bP[4];
#pragma unroll
            for (int m = 0; m < 4; m++) aP[m] = *(const u64*)&sa[ty + m * 16][hp * 2];
#pragma unroll
            for (int n = 0; n < 4; n++) bP[n] = *(const u64*)&sb[tx + n * 16][hp * 2];
#pragma unroll
            for (int m = 0; m < 4; m++)
#pragma unroll
                for (int n = 0; n < 4; n++) {
                    u64 s = add2(aP[m], bP[n]) & 0x7FFFFFFF7FFFFFFFull;  // |a+b| packed
                    fma2(acc[m][n], s, wP);
                }
        }
    }

    const float bw = bwe2[0];
#pragma unroll
    for (int m = 0; m < 4; m++) {
        const int il = ty + m * 16;
        const int i = I + il;
        const float cv = sci[il] + bw;
        const int la = li[il];
#pragma unroll
        for (int n = 0; n < 4; n++) {
            const int jl = tx + n * 16;
            const int j = J + jl;
            float2 p = unpack2(acc[m][n]);
            float logit = p.x + p.y + cv + sdj[jl];
            float e = (la == lj[jl] && i != j) ? 1.f / (1.f + expf(-logit)) : 0.f;
            E[(size_t)i * NN + j] = e;
        }
    }
}

// ---------------- deterministic row sum of E --------------------------------
__global__ void row_sum(const float* __restrict__ E, float* __restrict__ wsum) {
    const int i = blockIdx.x;
    const int t = threadIdx.x;  // 256
    float4 v = ((const float4*)(E + (size_t)i * NN))[t];
    float s = v.x + v.y + v.z + v.w;
#pragma unroll
    for (int o = 16; o > 0; o >>= 1) s += __shfl_xor_sync(~0u, s, o);
    __shared__ float sm[8];
    if ((t & 31) == 0) sm[t >> 5] = s;
    __syncthreads();
    if (t == 0) {
        float S = 0.f;
#pragma unroll
        for (int k = 0; k < 8; k++) S += sm[k];
        wsum[i] = S;
    }
}

// ---------------- final reduce: out = di + (P0+P1) / wsum -------------------
__global__ void reduce_epi(const float* __restrict__ P, const float* __restrict__ di,
                           const float* __restrict__ ws, float* __restrict__ out) {
    const int idx = blockIdx.x * 256 + threadIdx.x;  // float4 index
    const int row = idx >> 6;
    float w = ws[row];
    float inv = w > 0.f ? 1.f / w : 0.f;
    constexpr int Q = NN * H / 4;
    float4 a = ((const float4*)P)[idx];
    float4 b = ((const float4*)P)[Q + idx];
    float4 d = ((const float4*)di)[idx];
    float4 o;
    o.x = fmaf(a.x + b.x, inv, d.x);
    o.y = fmaf(a.y + b.y, inv, d.y);
    o.z = fmaf(a.z + b.z, inv, d.z);
    o.w = fmaf(a.w + b.w, inv, d.w);
    ((float4*)out)[idx] = o;
}

// ---------------- launch -----------------------------------------------------
extern "C" void kernel_launch(void* const* d_in, const int* in_sizes, int n_in,
                              void* d_out, int out_size) {
    const float* features = (const float*)d_in[0];
    const int* labels = (const int*)d_in[1];
    const float* W1 = (const float*)d_in[2];
    const float* b1 = (const float*)d_in[3];
    const float* g1 = (const float*)d_in[4];
    const float* bt1 = (const float*)d_in[5];
    const float* W2 = (const float*)d_in[6];
    const float* b2 = (const float*)d_in[7];
    const float* g2 = (const float*)d_in[8];
    const float* bt2 = (const float*)d_in[9];
    const float* We1 = (const float*)d_in[10];
    const float* bwe1 = (const float*)d_in[11];
    const float* We2 = (const float*)d_in[12];
    const float* bwe2 = (const float*)d_in[13];
    float* out = (float*)d_out;

    void *pP, *ph, *pdi, *phi, *phjb, *pE, *psc, *psh, *pci, *pdj, *pws;
    cudaGetSymbolAddress(&pP, g_P);
    cudaGetSymbolAddress(&ph, g_h);
    cudaGetSymbolAddress(&pdi, g_di);
    cudaGetSymbolAddress(&phi, g_hi);
    cudaGetSymbolAddress(&phjb, g_hjb);
    cudaGetSymbolAddress(&pE, g_E);
    cudaGetSymbolAddress(&psc, g_sc);
    cudaGetSymbolAddress(&psh, g_sh);
    cudaGetSymbolAddress(&pci, g_ci);
    cudaGetSymbolAddress(&pdj, g_dj);
    cudaGetSymbolAddress(&pws, g_wsum);

    float* P = (float*)pP;
    float* h = (float*)ph;
    float* di = (float*)pdi;
    float* hi = (float*)phi;
    float* hjb = (float*)phjb;
    float* E = (float*)pE;
    float* sc = (float*)psc;
    float* sh = (float*)psh;
    float* ci = (float*)pci;
    float* dj = (float*)pdj;
    float* ws = (float*)pws;

    // 1) P[0..3] = split-K partials of features @ W1
    gemm_v2<64, 1><<<dim3(4, 16, 4), 256>>>(features, W1, P, nullptr, 2048, 512, nullptr, nullptr);
    // 2) BN1 stats from partials (+b1)
    bn_stats_part<<<8, 512>>>(P, b1, g1, bt1, sc, sh);
    // 3) h = relu(BN1)
    bn_apply_part<<<256, 256>>>(P, b1, sc, sh, h);
    // 4) P[0..3] = split-K partials of h @ W2
    gemm_v2<64, 1><<<dim3(4, 16, 4), 256>>>(h, W2, P, nullptr, 256, 64, nullptr, nullptr);
    // 5) BN2 stats (+b2)
    bn_stats_part<<<8, 512>>>(P, b2, g2, bt2, sc, sh);
    // 6) di = relu(BN2)
    bn_apply_part<<<256, 256>>>(P, b2, sc, sh, di);
    // 7) hi = di @ We1[:H] ; hjb = di @ We1[H:] + bwe1   (dual via z)
    gemm_v2<32, 2><<<dim3(4, 32, 2), 128>>>(di, We1, hi, hjb, 256, 0, nullptr, bwe1);
    // 8) ci/dj GEMVs
    cidj_kernel<<<256, 256>>>(hi, hjb, We2, ci, dj);
    // 9) edge weights
    edge_kernel<<<dim3(16, 16), 256>>>(hi, hjb, We2, bwe2, labels, ci, dj, E);
    // 10) row sums
    row_sum<<<NN, 256>>>(E, ws);
    // 11) P[0..1] = split-K partials of E @ di
    gemm_v2<32, 1><<<dim3(4, 32, 2), 128>>>(E, di, P, nullptr, 1024, 512, nullptr, nullptr);
    // 12) out = di + (P0+P1)/wsum
    reduce_epi<<<256, 256>>>(P, di, ws, out);
}

// round 3
// speedup vs baseline: 1.6240x; 1.1338x over previous
#include <cuda_runtime.h>
#include <cuda_bf16.h>
#include <math.h>

#define NN 1024
#define H 256

typedef unsigned long long u64;

// ---------------- f32x2 packed helpers (sm_103a) ----------------------------
__device__ __forceinline__ u64 add2(u64 a, u64 b) {
    u64 r; asm("add.rn.f32x2 %0,%1,%2;" : "=l"(r) : "l"(a), "l"(b)); return r;
}
__device__ __forceinline__ void fma2(u64& d, u64 a, u64 b) {
    asm("fma.rn.f32x2 %0,%1,%2,%0;" : "+l"(d) : "l"(a), "l"(b));
}
__device__ __forceinline__ float2 unpack2(u64 v) {
    float2 r; asm("mov.b64 {%0,%1},%2;" : "=f"(r.x), "=f"(r.y) : "l"(v)); return r;
}

// ---------------- scratch ----------------------------------------------------
__device__ float g_P[4 * NN * H];
__device__ float g_Q[2 * NN * H];
__device__ float g_X1[NN * H];
__device__ float g_X2[NN * H];
__device__ float g_di[NN * H];
__device__ float g_hi[NN * H];
__device__ float g_hjb[NN * H];
__device__ float g_E[NN * NN];
__device__ float g_S[128 * 512];
__device__ float g_sc[H], g_sh[H];
__device__ float g_ci[NN], g_dj[NN];
__device__ float g_ws[NN];

// ---------------- GEMM: C[1024,256] = A[1024,K] @ B[K,256] ------------------
// Tile 32x64, BK=16, 128 threads, 4x4 per thread, double-buffered smem,
// K-packed f32x2 accumulation.
// MODE 1: split-K, z-th chunk (len KS) -> C0 + z*NN*H
// MODE 0: dual: z=0 -> C0 = A@B[:256]; z=1 -> C1 = A@B[256:] + bias1
// BNA: transform A elements on load: relu(fma(a, bnsc[k], bnsh[k]))
template <int MODE, bool BNA>
__global__ __launch_bounds__(128) void gemm_k(
    const float* __restrict__ A, const float* __restrict__ B,
    float* __restrict__ C0, float* __restrict__ C1, int K, int KS,
    const float* __restrict__ bias1,
    const float* __restrict__ bnsc, const float* __restrict__ bnsh) {
    __shared__ float As[2][32][18];
    __shared__ float Bs[2][64][18];

    const int t = threadIdx.x;
    const int tx = t & 15;
    const int ty = t >> 4;  // 0..7
    const int I = blockIdx.y * 32;
    const int J = blockIdx.x * 64;
    const int z = blockIdx.z;

    const float* Bp = B;
    float* Cp = C0;
    const float* bp = nullptr;
    int kbase = 0;
    if (MODE == 1) {
        kbase = z * KS;
        Cp = C0 + (size_t)z * NN * H;
    } else {
        if (z) { Bp = B + H * H; Cp = C1; bp = bias1; }
    }

    const int kiters = KS >> 4;
    float ra[4], rb[8];

    auto loadA = [&](int kt) {
        const int c = t & 15;
        const int kc = kbase + kt * 16 + c;
        float scv = 0.f, shv = 0.f;
        if (BNA) { scv = bnsc[kc]; shv = bnsh[kc]; }
#pragma unroll
        for (int e = 0; e < 4; e++) {
            int r = (t >> 4) + e * 8;
            float v = A[(size_t)(I + r) * K + kc];
            if (BNA) v = fmaxf(fmaf(v, scv, shv), 0.f);
            ra[e] = v;
        }
    };
    auto loadB = [&](int kt) {
        const int c = t & 63;
        const int r0 = t >> 6;
#pragma unroll
        for (int e = 0; e < 8; e++) {
            int r = r0 + e * 2;
            rb[e] = Bp[(size_t)(kbase + kt * 16 + r) * H + J + c];
        }
    };
    auto stageS = [&](int buf) {
        const int ca = t & 15;
#pragma unroll
        for (int e = 0; e < 4; e++) As[buf][(t >> 4) + e * 8][ca] = ra[e];
        const int cb = t & 63;
        const int r0 = t >> 6;
#pragma unroll
        for (int e = 0; e < 8; e++) Bs[buf][cb][r0 + e * 2] = rb[e];
    };

    u64 acc[4][4];
#pragma unroll
    for (int m = 0; m < 4; m++)
#pragma unroll
        for (int n = 0; n < 4; n++) acc[m][n] = 0ull;

    loadA(0); loadB(0);
    stageS(0);
    __syncthreads();

    for (int kt = 0; kt < kiters; kt++) {
        const int buf = kt & 1;
        if (kt + 1 < kiters) { loadA(kt + 1); loadB(kt + 1); }
#pragma unroll
        for (int kp = 0; kp < 8; kp++) {
            u64 aP[4], bP[4];
#pragma unroll
            for (int m = 0; m < 4; m++)
                aP[m] = *(const u64*)&As[buf][ty * 4 + m][kp * 2];
#pragma unroll
            for (int n = 0; n < 4; n++)
                bP[n] = *(const u64*)&Bs[buf][tx + n * 16][kp * 2];
#pragma unroll
            for (int m = 0; m < 4; m++)
#pragma unroll
                for (int n = 0; n < 4; n++) fma2(acc[m][n], aP[m], bP[n]);
        }
        if (kt + 1 < kiters) {
            stageS(buf ^ 1);
            __syncthreads();
        }
    }

#pragma unroll
    for (int m = 0; m < 4; m++) {
        const int row = I + ty * 4 + m;
#pragma unroll
        for (int n = 0; n < 4; n++) {
            const int col = J + tx + n * 16;
            float2 p = unpack2(acc[m][n]);
            float v = p.x + p.y;
            if (MODE == 0 && bp) v += bp[col];
            Cp[(size_t)row * H + col] = v;
        }
    }
}

// ---------------- BN stats phase1: X = sum(P)+bias, partial s/sq ------------
// 128 blocks x 256 thr; block handles 8 rows of all 256 cols.
template <int NP>
__global__ void stats_phase1(const float* __restrict__ P, const float* __restrict__ bias,
                             float* __restrict__ X, float* __restrict__ S) {
    const int t = threadIdx.x;
    const int c4 = t & 63;
    const int rg = t >> 6;  // 0..3
    const int row0 = blockIdx.x * 8 + rg * 2;
    float4 bv = ((const float4*)bias)[c4];
    float4 s = make_float4(0.f, 0.f, 0.f, 0.f);
    float4 q = make_float4(0.f, 0.f, 0.f, 0.f);
#pragma unroll
    for (int rr = 0; rr < 2; rr++) {
        size_t idx = (size_t)(row0 + rr) * 64 + c4;
        float4 v = bv;
#pragma unroll
        for (int p = 0; p < NP; p++) {
            float4 a = ((const float4*)P)[(size_t)p * (NN * H / 4) + idx];
            v.x += a.x; v.y += a.y; v.z += a.z; v.w += a.w;
        }
        ((float4*)X)[idx] = v;
        s.x += v.x; s.y += v.y; s.z += v.z; s.w += v.w;
        q.x += v.x * v.x; q.y += v.y * v.y; q.z += v.z * v.z; q.w += v.w * v.w;
    }
    __shared__ float4 sm[4][64], qm[4][64];
    sm[rg][c4] = s;
    qm[rg][c4] = q;
    __syncthreads();
    if (t < 64) {
        float4 S4 = make_float4(0.f, 0.f, 0.f, 0.f);
        float4 Q4 = make_float4(0.f, 0.f, 0.f, 0.f);
#pragma unroll
        for (int p = 0; p < 4; p++) {
            float4 a = sm[p][t], b = qm[p][t];
            S4.x += a.x; S4.y += a.y; S4.z += a.z; S4.w += a.w;
            Q4.x += b.x; Q4.y += b.y; Q4.z += b.z; Q4.w += b.w;
        }
        ((float4*)S)[blockIdx.x * 128 + t] = S4;
        ((float4*)S)[blockIdx.x * 128 + 64 + t] = Q4;
    }
}

// ---------------- BN stats phase2: finalize scale/shift ---------------------
__global__ void stats_phase2(const float* __restrict__ S, const float* __restrict__ g,
                             const float* __restrict__ bt, float* __restrict__ sc,
                             float* __restrict__ sh) {
    const int t = threadIdx.x;
    const int c = blockIdx.x * 32 + (t & 31);
    const int pg = t >> 5;  // 0..7
    float s = 0.f, q = 0.f;
#pragma unroll
    for (int p = pg; p < 128; p += 8) {
        s += S[p * 512 + c];
        q += S[p * 512 + 256 + c];
    }
    __shared__ float sm[8][32], qm[8][32];
    sm[pg][t & 31] = s;
    qm[pg][t & 31] = q;
    __syncthreads();
    if (t < 32) {
        float S_ = 0.f, Q_ = 0.f;
#pragma unroll
        for (int p = 0; p < 8; p++) { S_ += sm[p][t]; Q_ += qm[p][t]; }
        const int col = blockIdx.x * 32 + t;
        float m = S_ * (1.f / NN);
        float var = Q_ * (1.f / NN) - m * m;
        float scv = g[col] * rsqrtf(var + 1e-5f);
        sc[col] = scv;
        sh[col] = bt[col] - m * scv;
    }
}

// ---------------- apply: Y = relu(fma(X, sc, sh)) ---------------------------
__global__ void apply_relu(const float* __restrict__ X, const float* __restrict__ sc,
                           const float* __restrict__ sh, float* __restrict__ Y) {
    const int idx = blockIdx.x * 256 + threadIdx.x;
    const int c4 = idx & 63;
    float4 v = ((const float4*)X)[idx];
    float4 s = ((const float4*)sc)[c4];
    float4 h = ((const float4*)sh)[c4];
    float4 y;
    y.x = fmaxf(fmaf(v.x, s.x, h.x), 0.f);
    y.y = fmaxf(fmaf(v.y, s.y, h.y), 0.f);
    y.z = fmaxf(fmaf(v.z, s.z, h.z), 0.f);
    y.w = fmaxf(fmaf(v.w, s.w, h.w), 0.f);
    ((float4*)Y)[idx] = y;
}

// ---------------- ci / dj GEMVs: 0.5 * (rows @ We2) --------------------------
__global__ void cidj_kernel(const float* __restrict__ hi, const float* __restrict__ hjb,
                            const float* __restrict__ We2,
                            float* __restrict__ ci, float* __restrict__ dj) {
    const int gt = blockIdx.x * 256 + threadIdx.x;
    const int w = gt >> 5;
    const int lane = gt & 31;
    const float* src = (w < NN) ? hi : hjb;
    const int row = (w < NN) ? w : w - NN;
    float s = 0.f;
#pragma unroll
    for (int e = 0; e < 8; e++) {
        int c = lane + e * 32;
        s = fmaf(src[(size_t)row * H + c], We2[c], s);
    }
#pragma unroll
    for (int o = 16; o > 0; o >>= 1) s += __shfl_xor_sync(~0u, s, o);
    if (lane == 0) ((w < NN) ? ci : dj)[row] = 0.5f * s;
}

// ---------------- Edge kernel: 32x64 tile, double-buffered ------------------
// logit = 0.5*sum_h w*|a+b| + ci[i] + dj[j] + bwe2
__global__ __launch_bounds__(128, 4) void edge_kernel(
    const float* __restrict__ hi, const float* __restrict__ hjb,
    const float* __restrict__ We2, const float* __restrict__ bwe2,
    const int* __restrict__ labels,
    const float* __restrict__ ci, const float* __restrict__ dj,
    float* __restrict__ E) {
    __shared__ float sa[2][32][66];
    __shared__ float sb[2][64][66];
    __shared__ float sw[256];
    __shared__ int li[32], lj[64];
    __shared__ float sci[32], sdj[64];

    const int t = threadIdx.x;
    const int tx = t & 15;
    const int ty = t >> 4;  // 0..7
    const int I = blockIdx.y * 32;
    const int J = blockIdx.x * 64;

    if (t < 32) { li[t] = labels[I + t]; sci[t] = ci[I + t]; }
    if (t < 64) { lj[t] = labels[J + t]; sdj[t] = dj[J + t]; }
    sw[t] = 0.5f * We2[t];
    sw[t + 128] = 0.5f * We2[t + 128];

    float4 fa[4], fb[8];
    const int ra_ = t >> 2, ca_ = (t & 3) * 16;
    const int rb_ = t >> 1, cb_ = (t & 1) * 32;

    auto loadG = [&](int hc) {
#pragma unroll
        for (int e = 0; e < 4; e++)
            fa[e] = *(const float4*)&hi[(size_t)(I + ra_) * H + hc + ca_ + e * 4];
#pragma unroll
        for (int e = 0; e < 8; e++)
            fb[e] = *(const float4*)&hjb[(size_t)(J + rb_) * H + hc + cb_ + e * 4];
    };
    auto stageS = [&](int buf) {
#pragma unroll
        for (int e = 0; e < 4; e++) {
            *(float2*)&sa[buf][ra_][ca_ + e * 4] = make_float2(fa[e].x, fa[e].y);
            *(float2*)&sa[buf][ra_][ca_ + e * 4 + 2] = make_float2(fa[e].z, fa[e].w);
        }
#pragma unroll
        for (int e = 0; e < 8; e++) {
            *(float2*)&sb[buf][rb_][cb_ + e * 4] = make_float2(fb[e].x, fb[e].y);
            *(float2*)&sb[buf][rb_][cb_ + e * 4 + 2] = make_float2(fb[e].z, fb[e].w);
        }
    };

    u64 acc[4][4];
#pragma unroll
    for (int m = 0; m < 4; m++)
#pragma unroll
        for (int n = 0; n < 4; n++) acc[m][n] = 0ull;

    loadG(0);
    stageS(0);
    __syncthreads();

    for (int c = 0; c < 4; c++) {
        const int buf = c & 1;
        if (c < 3) loadG((c + 1) * 64);
        const int hb = c * 64;
#pragma unroll 8
        for (int hp = 0; hp < 32; hp++) {
            u64 wP = *(const u64*)&sw[hb + hp * 2];
            u64 aP[4], bP[4];
#pragma unroll
            for (int m = 0; m < 4; m++) aP[m] = *(const u64*)&sa[buf][ty + m * 8][hp * 2];
#pragma unroll
            for (int n = 0; n < 4; n++) bP[n] = *(const u64*)&sb[buf][tx + n * 16][hp * 2];
#pragma unroll
            for (int m = 0; m < 4; m++)
#pragma unroll
                for (int n = 0; n < 4; n++) {
                    u64 s = add2(aP[m], bP[n]) & 0x7FFFFFFF7FFFFFFFull;
                    fma2(acc[m][n], s, wP);
                }
        }
        if (c < 3) {
            stageS(buf ^ 1);
            __syncthreads();
        }
    }

    const float bw = bwe2[0];
#pragma unroll
    for (int m = 0; m < 4; m++) {
        const int il = ty + m * 8;
        const int i = I + il;
        const int la = li[il];
        const float cv = sci[il] + bw;
#pragma unroll
        for (int n = 0; n < 4; n++) {
            const int jl = tx + n * 16;
            const int j = J + jl;
            float2 p = unpack2(acc[m][n]);
            float logit = p.x + p.y + cv + sdj[jl];
            float e = (la == lj[jl] && i != j) ? 1.f / (1.f + expf(-logit)) : 0.f;
            E[(size_t)i * NN + j] = e;
        }
    }
}

// ---------------- deterministic row sum of E --------------------------------
__global__ void row_sum(const float* __restrict__ E, float* __restrict__ wsum) {
    const int i = blockIdx.x;
    const int t = threadIdx.x;
    float4 v = ((const float4*)(E + (size_t)i * NN))[t];
    float s = v.x + v.y + v.z + v.w;
#pragma unroll
    for (int o = 16; o > 0; o >>= 1) s += __shfl_xor_sync(~0u, s, o);
    __shared__ float sm[8];
    if ((t & 31) == 0) sm[t >> 5] = s;
    __syncthreads();
    if (t == 0) {
        float S = 0.f;
#pragma unroll
        for (int k = 0; k < 8; k++) S += sm[k];
        wsum[i] = S;
    }
}

// ---------------- final: out = di + (P0+P1+P2+P3)/wsum ----------------------
__global__ void reduce_epi(const float* __restrict__ P, const float* __restrict__ di,
                           const float* __restrict__ ws, float* __restrict__ out) {
    const int idx = blockIdx.x * 256 + threadIdx.x;
    const int row = idx >> 6;
    float w = ws[row];
    float inv = w > 0.f ? 1.f / w : 0.f;
    constexpr int Q = NN * H / 4;
    float4 a = ((const float4*)P)[idx];
    float4 b = ((const float4*)P)[Q + idx];
    float4 c = ((const float4*)P)[2 * Q + idx];
    float4 d = ((const float4*)P)[3 * Q + idx];
    float4 di4 = ((const float4*)di)[idx];
    float4 o;
    o.x = fmaf(a.x + b.x + c.x + d.x, inv, di4.x);
    o.y = fmaf(a.y + b.y + c.y + d.y, inv, di4.y);
    o.z = fmaf(a.z + b.z + c.z + d.z, inv, di4.z);
    o.w = fmaf(a.w + b.w + c.w + d.w, inv, di4.w);
    ((float4*)out)[idx] = o;
}

// ---------------- launch -----------------------------------------------------
extern "C" void kernel_launch(void* const* d_in, const int* in_sizes, int n_in,
                              void* d_out, int out_size) {
    const float* features = (const float*)d_in[0];
    const int* labels = (const int*)d_in[1];
    const float* W1 = (const float*)d_in[2];
    const float* b1 = (const float*)d_in[3];
    const float* g1 = (const float*)d_in[4];
    const float* bt1 = (const float*)d_in[5];
    const float* W2 = (const float*)d_in[6];
    const float* b2 = (const float*)d_in[7];
    const float* g2 = (const float*)d_in[8];
    const float* bt2 = (const float*)d_in[9];
    const float* We1 = (const float*)d_in[10];
    const float* bwe1 = (const float*)d_in[11];
    const float* We2 = (const float*)d_in[12];
    const float* bwe2 = (const float*)d_in[13];
    float* out = (float*)d_out;

    void *pP, *pQ, *pX1, *pX2, *pdi, *phi, *phjb, *pE, *pS, *psc, *psh, *pci, *pdj, *pws;
    cudaGetSymbolAddress(&pP, g_P);
    cudaGetSymbolAddress(&pQ, g_Q);
    cudaGetSymbolAddress(&pX1, g_X1);
    cudaGetSymbolAddress(&pX2, g_X2);
    cudaGetSymbolAddress(&pdi, g_di);
    cudaGetSymbolAddress(&phi, g_hi);
    cudaGetSymbolAddress(&phjb, g_hjb);
    cudaGetSymbolAddress(&pE, g_E);
    cudaGetSymbolAddress(&pS, g_S);
    cudaGetSymbolAddress(&psc, g_sc);
    cudaGetSymbolAddress(&psh, g_sh);
    cudaGetSymbolAddress(&pci, g_ci);
    cudaGetSymbolAddress(&pdj, g_dj);
    cudaGetSymbolAddress(&pws, g_ws);

    float* P = (float*)pP;
    float* Q = (float*)pQ;
    float* X1 = (float*)pX1;
    float* X2 = (float*)pX2;
    float* di = (float*)pdi;
    float* hi = (float*)phi;
    float* hjb = (float*)phjb;
    float* E = (float*)pE;
    float* S = (float*)pS;
    float* sc = (float*)psc;
    float* sh = (float*)psh;
    float* ci = (float*)pci;
    float* dj = (float*)pdj;
    float* ws = (float*)pws;

    // 1) split-K4 partials of features @ W1
    gemm_k<1, false><<<dim3(4, 32, 4), 128>>>(features, W1, P, nullptr, 2048, 512,
                                              nullptr, nullptr, nullptr);
    // 2) X1 = sum(P)+b1 ; BN1 stats partials
    stats_phase1<4><<<128, 256>>>(P, b1, X1, S);
    stats_phase2<<<8, 256>>>(S, g1, bt1, sc, sh);
    // 3) Q = relu(BN1(X1)) @ W2, split-K2, BN fused on A-load
    gemm_k<1, true><<<dim3(4, 32, 2), 128>>>(X1, W2, Q, nullptr, 256, 128,
                                             nullptr, sc, sh);
    // 4) X2 = sum(Q)+b2 ; BN2 stats
    stats_phase1<2><<<128, 256>>>(Q, b2, X2, S);
    stats_phase2<<<8, 256>>>(S, g2, bt2, sc, sh);
    // 5) di = relu(BN2(X2))
    apply_relu<<<256, 256>>>(X2, sc, sh, di);
    // 6) hi = di @ We1[:H] ; hjb = di @ We1[H:] + bwe1
    gemm_k<0, false><<<dim3(4, 32, 2), 128>>>(di, We1, hi, hjb, 256, 256,
                                              bwe1, nullptr, nullptr);
    // 7) ci/dj
    cidj_kernel<<<256, 256>>>(hi, hjb, We2, ci, dj);
    // 8) edge weights
    edge_kernel<<<dim3(16, 32), 128>>>(hi, hjb, We2, bwe2, labels, ci, dj, E);
    // 9) row sums
    row_sum<<<NN, 256>>>(E, ws);
    // 10) split-K4 partials of E @ di
    gemm_k<1, false><<<dim3(4, 32, 4), 128>>>(E, di, P, nullptr, 1024, 256,
                                              nullptr, nullptr, nullptr);
    // 11) out = di + sum(P)/wsum
    reduce_epi<<<256, 256>>>(P, di, ws, out);
}

// round 4
// speedup vs baseline: 1.8863x; 1.1615x over previous
#include <cuda_runtime.h>
#include <cuda_bf16.h>
#include <math.h>

#define NN 1024
#define H 256

typedef unsigned long long u64;

// ---------------- f32x2 packed helpers (sm_103a) ----------------------------
__device__ __forceinline__ u64 add2(u64 a, u64 b) {
    u64 r; asm("add.rn.f32x2 %0,%1,%2;" : "=l"(r) : "l"(a), "l"(b)); return r;
}
__device__ __forceinline__ void fma2(u64& d, u64 a, u64 b) {
    asm("fma.rn.f32x2 %0,%1,%2,%0;" : "+l"(d) : "l"(a), "l"(b));
}
__device__ __forceinline__ float2 unpack2(u64 v) {
    float2 r; asm("mov.b64 {%0,%1},%2;" : "=f"(r.x), "=f"(r.y) : "l"(v)); return r;
}

// ---------------- cp.async helpers ------------------------------------------
__device__ __forceinline__ void cp16(void* dst_smem, const void* src) {
    unsigned d = (unsigned)__cvta_generic_to_shared(dst_smem);
    asm volatile("cp.async.cg.shared.global [%0], [%1], 16;" :: "r"(d), "l"(src));
}
__device__ __forceinline__ void cp_commit() {
    asm volatile("cp.async.commit_group;" ::: "memory");
}
template <int N>
__device__ __forceinline__ void cp_wait() {
    asm volatile("cp.async.wait_group %0;" :: "n"(N) : "memory");
}

// ---------------- scratch ----------------------------------------------------
__device__ float g_P[8 * NN * H];
__device__ float g_Q[4 * NN * H];
__device__ float g_X1[NN * H];
__device__ float g_X2[NN * H];
__device__ float g_di[NN * H];
__device__ float g_hi[NN * H];
__device__ float g_hjb[NN * H];
__device__ float g_E[NN * NN];
__device__ float g_S[256 * 512];
__device__ float g_sc[H], g_sh[H];
__device__ float g_ci[NN], g_dj[NN];
__device__ float g_ws[NN];

// ---------------- GEMM: split-K partials, tile 32x64, 128 thr ---------------
// DUAL: z>>1 selects B half (B + half*H*H), z&1 selects K chunk.
// else: z selects K chunk. Output plane = z (C0 + z*NN*H).
// BNA: A elements transformed on load: relu(fma(a, bnsc[k], bnsh[k])).
template <bool DUAL, bool BNA>
__global__ __launch_bounds__(128) void gemm_k(
    const float* __restrict__ A, const float* __restrict__ B,
    float* __restrict__ C0, int K, int KS,
    const float* __restrict__ bnsc, const float* __restrict__ bnsh) {
    __shared__ float As[2][32][18];
    __shared__ float Bs[2][64][18];

    const int t = threadIdx.x;
    const int tx = t & 15;
    const int ty = t >> 4;
    const int I = blockIdx.y * 32;
    const int J = blockIdx.x * 64;
    const int z = blockIdx.z;

    const float* Bp = DUAL ? (B + (size_t)(z >> 1) * H * H) : B;
    const int kbase = (DUAL ? (z & 1) : z) * KS;
    float* Cp = C0 + (size_t)z * NN * H;

    const int kiters = KS >> 4;
    float ra[4], rb[8];

    auto loadA = [&](int kt) {
        const int c = t & 15;
        const int kc = kbase + kt * 16 + c;
        float scv = 0.f, shv = 0.f;
        if (BNA) { scv = bnsc[kc]; shv = bnsh[kc]; }
#pragma unroll
        for (int e = 0; e < 4; e++) {
            int r = (t >> 4) + e * 8;
            float v = A[(size_t)(I + r) * K + kc];
            if (BNA) v = fmaxf(fmaf(v, scv, shv), 0.f);
            ra[e] = v;
        }
    };
    auto loadB = [&](int kt) {
        const int c = t & 63;
        const int r0 = t >> 6;
#pragma unroll
        for (int e = 0; e < 8; e++) {
            int r = r0 + e * 2;
            rb[e] = Bp[(size_t)(kbase + kt * 16 + r) * H + J + c];
        }
    };
    auto stageS = [&](int buf) {
        const int ca = t & 15;
#pragma unroll
        for (int e = 0; e < 4; e++) As[buf][(t >> 4) + e * 8][ca] = ra[e];
        const int cb = t & 63;
        const int r0 = t >> 6;
#pragma unroll
        for (int e = 0; e < 8; e++) Bs[buf][cb][r0 + e * 2] = rb[e];
    };

    u64 acc[4][4];
#pragma unroll
    for (int m = 0; m < 4; m++)
#pragma unroll
        for (int n = 0; n < 4; n++) acc[m][n] = 0ull;

    loadA(0); loadB(0);
    stageS(0);
    __syncthreads();

    for (int kt = 0; kt < kiters; kt++) {
        const int buf = kt & 1;
        if (kt + 1 < kiters) { loadA(kt + 1); loadB(kt + 1); }
#pragma unroll
        for (int kp = 0; kp < 8; kp++) {
            u64 aP[4], bP[4];
#pragma unroll
            for (int m = 0; m < 4; m++)
                aP[m] = *(const u64*)&As[buf][ty * 4 + m][kp * 2];
#pragma unroll
            for (int n = 0; n < 4; n++)
                bP[n] = *(const u64*)&Bs[buf][tx + n * 16][kp * 2];
#pragma unroll
            for (int m = 0; m < 4; m++)
#pragma unroll
                for (int n = 0; n < 4; n++) fma2(acc[m][n], aP[m], bP[n]);
        }
        if (kt + 1 < kiters) {
            stageS(buf ^ 1);
            __syncthreads();
        }
    }

#pragma unroll
    for (int m = 0; m < 4; m++) {
        const int row = I + ty * 4 + m;
#pragma unroll
        for (int n = 0; n < 4; n++) {
            const int col = J + tx + n * 16;
            float2 p = unpack2(acc[m][n]);
            Cp[(size_t)row * H + col] = p.x + p.y;
        }
    }
}

// ---------------- BN stats phase1: X = sum(P)+bias, partial s/sq ------------
// 256 blocks x 256 thr; block handles 4 rows of all 256 cols.
template <int NP>
__global__ void stats_phase1(const float* __restrict__ P, const float* __restrict__ bias,
                             float* __restrict__ X, float* __restrict__ S) {
    const int t = threadIdx.x;
    const int c4 = t & 63;
    const int rg = t >> 6;  // 0..3
    const int row = blockIdx.x * 4 + rg;
    float4 bv = ((const float4*)bias)[c4];
    constexpr size_t Q = NN * H / 4;
    size_t idx = (size_t)row * 64 + c4;
    float4 v = bv;
#pragma unroll
    for (int p = 0; p < NP; p++) {
        float4 a = ((const float4*)P)[(size_t)p * Q + idx];
        v.x += a.x; v.y += a.y; v.z += a.z; v.w += a.w;
    }
    ((float4*)X)[idx] = v;
    float4 q;
    q.x = v.x * v.x; q.y = v.y * v.y; q.z = v.z * v.z; q.w = v.w * v.w;
    __shared__ float4 sm[4][64], qm[4][64];
    sm[rg][c4] = v;
    qm[rg][c4] = q;
    __syncthreads();
    if (t < 64) {
        float4 S4 = make_float4(0.f, 0.f, 0.f, 0.f);
        float4 Q4 = make_float4(0.f, 0.f, 0.f, 0.f);
#pragma unroll
        for (int p = 0; p < 4; p++) {
            float4 a = sm[p][t], b = qm[p][t];
            S4.x += a.x; S4.y += a.y; S4.z += a.z; S4.w += a.w;
            Q4.x += b.x; Q4.y += b.y; Q4.z += b.z; Q4.w += b.w;
        }
        ((float4*)S)[blockIdx.x * 128 + t] = S4;
        ((float4*)S)[blockIdx.x * 128 + 64 + t] = Q4;
    }
}

// ---------------- BN stats phase2: finalize scale/shift ---------------------
__global__ void stats_phase2(const float* __restrict__ S, const float* __restrict__ g,
                             const float* __restrict__ bt, float* __restrict__ sc,
                             float* __restrict__ sh) {
    const int t = threadIdx.x;
    const int c = blockIdx.x * 32 + (t & 31);
    const int pg = t >> 5;  // 0..7
    float s = 0.f, q = 0.f;
#pragma unroll
    for (int p = pg; p < 256; p += 8) {
        s += S[p * 512 + c];
        q += S[p * 512 + 256 + c];
    }
    __shared__ float sm[8][32], qm[8][32];
    sm[pg][t & 31] = s;
    qm[pg][t & 31] = q;
    __syncthreads();
    if (t < 32) {
        float S_ = 0.f, Q_ = 0.f;
#pragma unroll
        for (int p = 0; p < 8; p++) { S_ += sm[p][t]; Q_ += qm[p][t]; }
        const int col = blockIdx.x * 32 + t;
        float m = S_ * (1.f / NN);
        float var = Q_ * (1.f / NN) - m * m;
        float scv = g[col] * rsqrtf(var + 1e-5f);
        sc[col] = scv;
        sh[col] = bt[col] - m * scv;
    }
}

// ---------------- apply: Y = relu(fma(X, sc, sh)) ---------------------------
__global__ void apply_relu(const float* __restrict__ X, const float* __restrict__ sc,
                           const float* __restrict__ sh, float* __restrict__ Y) {
    const int idx = blockIdx.x * 256 + threadIdx.x;
    const int c4 = idx & 63;
    float4 v = ((const float4*)X)[idx];
    float4 s = ((const float4*)sc)[c4];
    float4 h = ((const float4*)sh)[c4];
    float4 y;
    y.x = fmaxf(fmaf(v.x, s.x, h.x), 0.f);
    y.y = fmaxf(fmaf(v.y, s.y, h.y), 0.f);
    y.z = fmaxf(fmaf(v.z, s.z, h.z), 0.f);
    y.w = fmaxf(fmaf(v.w, s.w, h.w), 0.f);
    ((float4*)Y)[idx] = y;
}

// ---------------- combine GEMM3 partials + ci/dj GEMVs ----------------------
// hi[r] = Q0[r]+Q1[r]; hjb[r] = Q2[r]+Q3[r]+bwe1; ci = 0.5*hi.We2; dj = 0.5*hjb.We2
__global__ void combine_cidj(const float* __restrict__ Q, const float* __restrict__ bwe1,
                             const float* __restrict__ We2,
                             float* __restrict__ hi, float* __restrict__ hjb,
                             float* __restrict__ ci, float* __restrict__ dj) {
    const int r = blockIdx.x;
    const int t = threadIdx.x;  // 0..255
    const bool isB = t >= 128;
    const int tt = t & 127;
    constexpr size_t PL = (size_t)NN * H;
    const float* P0 = Q + (isB ? 2 * PL : 0);
    const float* P1 = P0 + PL;
    float* dst = isB ? hjb : hi;
    float partial = 0.f;
#pragma unroll
    for (int e = 0; e < 2; e++) {
        const int c = tt + e * 128;
        float v = P0[(size_t)r * H + c] + P1[(size_t)r * H + c];
        if (isB) v += bwe1[c];
        dst[(size_t)r * H + c] = v;
        partial = fmaf(v, We2[c], partial);
    }
#pragma unroll
    for (int o = 16; o > 0; o >>= 1) partial += __shfl_xor_sync(~0u, partial, o);
    __shared__ float red[8];
    if ((t & 31) == 0) red[t >> 5] = partial;
    __syncthreads();
    if (t == 0) ci[r] = 0.5f * (red[0] + red[1] + red[2] + red[3]);
    if (t == 128) dj[r] = 0.5f * (red[4] + red[5] + red[6] + red[7]);
}

// ---------------- Edge kernel: 32x64 tile, cp.async double-buffered ----------
// logit = 0.5*sum_h w*|a+b| + ci[i] + dj[j] + bwe2
__global__ __launch_bounds__(128) void edge_kernel(
    const float* __restrict__ hi, const float* __restrict__ hjb,
    const float* __restrict__ We2, const float* __restrict__ bwe2,
    const int* __restrict__ labels,
    const float* __restrict__ ci, const float* __restrict__ dj,
    float* __restrict__ E) {
    __shared__ float sa[2][32][36];
    __shared__ float sb[2][64][36];
    __shared__ float sw[256];
    __shared__ int li[32], lj[64];
    __shared__ float sci[32], sdj[64];

    const int t = threadIdx.x;
    const int tx = t & 15;
    const int ty = t >> 4;  // 0..7
    const int I = blockIdx.y * 32;
    const int J = blockIdx.x * 64;

    sw[t] = 0.5f * We2[t];
    sw[t + 128] = 0.5f * We2[t + 128];
    if (t < 32) { li[t] = labels[I + t]; sci[t] = ci[I + t]; }
    if (t < 64) { lj[t] = labels[J + t]; sdj[t] = dj[J + t]; }

    // stage chunk c (32 h-values) into buffer c&1 via cp.async
    auto stage = [&](int c) {
        const int buf = c & 1;
        const int hoff = c * 32;
#pragma unroll
        for (int k = 0; k < 6; k++) {
            int p = t + k * 128;  // 0..767
            if (p < 256) {
                int r = p >> 3, q = p & 7;
                cp16(&sa[buf][r][q * 4], hi + (size_t)(I + r) * H + hoff + q * 4);
            } else {
                int p2 = p - 256;
                int r = p2 >> 3, q = p2 & 7;
                cp16(&sb[buf][r][q * 4], hjb + (size_t)(J + r) * H + hoff + q * 4);
            }
        }
    };

    u64 acc[4][4];
#pragma unroll
    for (int m = 0; m < 4; m++)
#pragma unroll
        for (int n = 0; n < 4; n++) acc[m][n] = 0ull;

    stage(0);
    cp_commit();

    for (int c = 0; c < 8; c++) {
        if (c < 7) {
            stage(c + 1);
            cp_commit();
            cp_wait<1>();
        } else {
            cp_wait<0>();
        }
        __syncthreads();
        const int buf = c & 1;
        const float* swc = &sw[c * 32];
#pragma unroll
        for (int hp = 0; hp < 16; hp++) {
            u64 wP = *(const u64*)&swc[hp * 2];
            u64 aP[4], bP[4];
#pragma unroll
            for (int m = 0; m < 4; m++) aP[m] = *(const u64*)&sa[buf][ty + m * 8][hp * 2];
#pragma unroll
            for (int n = 0; n < 4; n++) bP[n] = *(const u64*)&sb[buf][tx + n * 16][hp * 2];
#pragma unroll
            for (int m = 0; m < 4; m++)
#pragma unroll
                for (int n = 0; n < 4; n++) {
                    u64 s = add2(aP[m], bP[n]) & 0x7FFFFFFF7FFFFFFFull;
                    fma2(acc[m][n], s, wP);
                }
        }
        __syncthreads();
    }

    const float bw = bwe2[0];
#pragma unroll
    for (int m = 0; m < 4; m++) {
        const int il = ty + m * 8;
        const int i = I + il;
        const int la = li[il];
        const float cv = sci[il] + bw;
#pragma unroll
        for (int n = 0; n < 4; n++) {
            const int jl = tx + n * 16;
            const int j = J + jl;
            float2 p = unpack2(acc[m][n]);
            float logit = p.x + p.y + cv + sdj[jl];
            float e = (la == lj[jl] && i != j) ? 1.f / (1.f + expf(-logit)) : 0.f;
            E[(size_t)i * NN + j] = e;
        }
    }
}

// ---------------- deterministic row sum of E --------------------------------
__global__ void row_sum(const float* __restrict__ E, float* __restrict__ wsum) {
    const int i = blockIdx.x;
    const int t = threadIdx.x;
    float4 v = ((const float4*)(E + (size_t)i * NN))[t];
    float s = v.x + v.y + v.z + v.w;
#pragma unroll
    for (int o = 16; o > 0; o >>= 1) s += __shfl_xor_sync(~0u, s, o);
    __shared__ float sm[8];
    if ((t & 31) == 0) sm[t >> 5] = s;
    __syncthreads();
    if (t == 0) {
        float S = 0.f;
#pragma unroll
        for (int k = 0; k < 8; k++) S += sm[k];
        wsum[i] = S;
    }
}

// ---------------- final: out = di + sum(P planes)/wsum ----------------------
__global__ void reduce_epi(const float* __restrict__ P, const float* __restrict__ di,
                           const float* __restrict__ ws, float* __restrict__ out) {
    const int idx = blockIdx.x * 256 + threadIdx.x;
    const int row = idx >> 6;
    float w = ws[row];
    float inv = w > 0.f ? 1.f / w : 0.f;
    constexpr size_t Q = NN * H / 4;
    float4 s = make_float4(0.f, 0.f, 0.f, 0.f);
#pragma unroll
    for (int p = 0; p < 8; p++) {
        float4 a = ((const float4*)P)[p * Q + idx];
        s.x += a.x; s.y += a.y; s.z += a.z; s.w += a.w;
    }
    float4 d = ((const float4*)di)[idx];
    float4 o;
    o.x = fmaf(s.x, inv, d.x);
    o.y = fmaf(s.y, inv, d.y);
    o.z = fmaf(s.z, inv, d.z);
    o.w = fmaf(s.w, inv, d.w);
    ((float4*)out)[idx] = o;
}

// ---------------- launch -----------------------------------------------------
extern "C" void kernel_launch(void* const* d_in, const int* in_sizes, int n_in,
                              void* d_out, int out_size) {
    const float* features = (const float*)d_in[0];
    const int* labels = (const int*)d_in[1];
    const float* W1 = (const float*)d_in[2];
    const float* b1 = (const float*)d_in[3];
    const float* g1 = (const float*)d_in[4];
    const float* bt1 = (const float*)d_in[5];
    const float* W2 = (const float*)d_in[6];
    const float* b2 = (const float*)d_in[7];
    const float* g2 = (const float*)d_in[8];
    const float* bt2 = (const float*)d_in[9];
    const float* We1 = (const float*)d_in[10];
    const float* bwe1 = (const float*)d_in[11];
    const float* We2 = (const float*)d_in[12];
    const float* bwe2 = (const float*)d_in[13];
    float* out = (float*)d_out;

    void *pP, *pQ, *pX1, *pX2, *pdi, *phi, *phjb, *pE, *pS, *psc, *psh, *pci, *pdj, *pws;
    cudaGetSymbolAddress(&pP, g_P);
    cudaGetSymbolAddress(&pQ, g_Q);
    cudaGetSymbolAddress(&pX1, g_X1);
    cudaGetSymbolAddress(&pX2, g_X2);
    cudaGetSymbolAddress(&pdi, g_di);
    cudaGetSymbolAddress(&phi, g_hi);
    cudaGetSymbolAddress(&phjb, g_hjb);
    cudaGetSymbolAddress(&pE, g_E);
    cudaGetSymbolAddress(&pS, g_S);
    cudaGetSymbolAddress(&psc, g_sc);
    cudaGetSymbolAddress(&psh, g_sh);
    cudaGetSymbolAddress(&pci, g_ci);
    cudaGetSymbolAddress(&pdj, g_dj);
    cudaGetSymbolAddress(&pws, g_ws);

    float* P = (float*)pP;
    float* Q = (float*)pQ;
    float* X1 = (float*)pX1;
    float* X2 = (float*)pX2;
    float* di = (float*)pdi;
    float* hi = (float*)phi;
    float* hjb = (float*)phjb;
    float* E = (float*)pE;
    float* S = (float*)pS;
    float* sc = (float*)psc;
    float* sh = (float*)psh;
    float* ci = (float*)pci;
    float* dj = (float*)pdj;
    float* ws = (float*)pws;

    // 1) GEMM1: features @ W1, split-K 8 -> P planes 0..7
    gemm_k<false, false><<<dim3(4, 32, 8), 128>>>(features, W1, P, 2048, 256, nullptr, nullptr);
    // 2) X1 = sum(P)+b1; BN1 stats
    stats_phase1<8><<<256, 256>>>(P, b1, X1, S);
    stats_phase2<<<8, 256>>>(S, g1, bt1, sc, sh);
    // 3) GEMM2: relu(BN1(X1)) @ W2 (BN fused on A-load), split-K 4 -> Q planes 0..3
    gemm_k<false, true><<<dim3(4, 32, 4), 128>>>(X1, W2, Q, 256, 64, sc, sh);
    // 4) X2 = sum(Q)+b2; BN2 stats
    stats_phase1<4><<<256, 256>>>(Q, b2, X2, S);
    stats_phase2<<<8, 256>>>(S, g2, bt2, sc, sh);
    // 5) di = relu(BN2(X2))
    apply_relu<<<256, 256>>>(X2, sc, sh, di);
    // 6) GEMM3: di @ We1 dual halves, split-K 2 each -> Q planes 0..3
    gemm_k<true, false><<<dim3(4, 32, 4), 128>>>(di, We1, Q, 256, 128, nullptr, nullptr);
    // 7) combine partials -> hi, hjb (+bwe1); ci/dj GEMVs
    combine_cidj<<<NN, 256>>>(Q, bwe1, We2, hi, hjb, ci, dj);
    // 8) edge weights
    edge_kernel<<<dim3(16, 32), 128>>>(hi, hjb, We2, bwe2, labels, ci, dj, E);
    // 9) row sums
    row_sum<<<NN, 256>>>(E, ws);
    // 10) GEMM4: E @ di, split-K 8 -> P planes 0..7
    gemm_k<false, false><<<dim3(4, 32, 8), 128>>>(E, di, P, 1024, 128, nullptr, nullptr);
    // 11) out = di + sum(P)/wsum
    reduce_epi<<<256, 256>>>(P, di, ws, out);
}